// round 2
// baseline (speedup 1.0000x reference)
#include <cuda_runtime.h>
#include <cstdint>

#define N_  4
#define C_  128
#define H_  216
#define W_  384
#define HW_ (H_ * W_)          // 82944
#define NHW_ (N_ * HW_)        // 331776
#define TOTAL_ (N_ * C_ * HW_) // 42467328

#define PAD 4
#define ROW (C_ + PAD)         // 132 floats per smem row (float4-aligned)
#define WTILE 32
#define CTAS (N_ * H_ * (W_ / WTILE))  // 10368

// NHWC accumulation scratch (zero at module load; re-zeroed by gather kernel
// each iteration so graph replays are deterministic).
__device__ float g_scr[TOTAL_];
__device__ float g_oscr[NHW_];

__device__ __forceinline__ void red_add_v4(float* p, float a, float b, float c, float d) {
    asm volatile("red.global.add.v4.f32 [%0], {%1,%2,%3,%4};"
                 :: "l"(p), "f"(a), "f"(b), "f"(c), "f"(d) : "memory");
}
__device__ __forceinline__ void red_add_f32(float* p, float a) {
    asm volatile("red.global.add.f32 [%0], %1;" :: "l"(p), "f"(a) : "memory");
}

// ---------------------------------------------------------------------------
// Kernel 1: scatter.  CTA = 32 consecutive w of one (n, h) row.
// Load img NCHW coalesced -> smem [pix][c] -> per-pixel float4 RED scatter
// into NHWC scratch.  o accumulated per-pixel into g_oscr.
// ---------------------------------------------------------------------------
__global__ __launch_bounds__(256) void scatter_kernel(
    const float* __restrict__ img, const float* __restrict__ flo)
{
    __shared__ __align__(16) float tile[WTILE * ROW];

    const int bid  = blockIdx.x;
    const int n    = bid / (H_ * (W_ / WTILE));
    const int rem  = bid % (H_ * (W_ / WTILE));
    const int h    = rem / (W_ / WTILE);
    const int w0   = (rem % (W_ / WTILE)) * WTILE;
    const int tid  = threadIdx.x;
    const int lane = tid & 31;
    const int warp = tid >> 5;

    // load + transpose: tile[w][c] = img[n, c, h, w0+w]   (128B coalesced / warp)
    const float* src = img + ((size_t)n * C_ * H_ + h) * (size_t)W_ + w0;
    #pragma unroll
    for (int cb = 0; cb < C_; cb += 8) {
        int c = cb + warp;
        tile[lane * ROW + c] = src[(size_t)c * HW_ + lane];
    }
    __syncthreads();

    const float* flo_y = flo + ((size_t)n * 2) * HW_ + h * W_ + w0;      // col shift
    const float* flo_x = flo_y + HW_;                                     // row shift
    float* const base_n = g_scr + (size_t)n * HW_ * C_;
    float* const obase  = g_oscr + (size_t)n * HW_;

    // each warp: 4 pixels; lanes span the 128 channels as float4
    #pragma unroll
    for (int i = 0; i < 4; i++) {
        const int p = warp * 4 + i;
        const int w = w0 + p;

        const float fy = flo_y[p];      // shifts W
        const float fx = flo_x[p];      // shifts H
        const float x1f = floorf(fx), y1f = floorf(fy);
        const float dx = fx - x1f, dy = fy - y1f;
        const int th0 = h + (int)x1f;
        const int tw0 = w + (int)y1f;

        const float ex0 = __expf(-dx * dx);
        const float ex1 = __expf(-(dx - 1.f) * (dx - 1.f));
        const float ey0 = __expf(-dy * dy);
        const float ey1 = __expf(-(dy - 1.f) * (dy - 1.f));

        const float4 v = *(const float4*)&tile[p * ROW + lane * 4];

        #pragma unroll
        for (int ci = 0; ci < 2; ci++) {
            const int th = th0 + ci;
            if (th < 0 || th >= H_) continue;
            const float exi = ci ? ex1 : ex0;
            #pragma unroll
            for (int cj = 0; cj < 2; cj++) {
                const int tw = tw0 + cj;
                if (tw < 0 || tw >= W_) continue;
                const float wt = exi * (cj ? ey1 : ey0);
                float* dst = base_n + ((size_t)th * W_ + tw) * C_ + lane * 4;
                red_add_v4(dst, v.x * wt, v.y * wt, v.z * wt, v.w * wt);
                if (lane == 0)
                    red_add_f32(obase + th * W_ + tw, wt);
            }
        }
    }
}

// ---------------------------------------------------------------------------
// Kernel 2: gather.  Read NHWC scratch (coalesced), zero it behind the read,
// transpose to NCHW imgw output, broadcast o to all 128 channels.
// ---------------------------------------------------------------------------
__global__ __launch_bounds__(256) void gather_kernel(float* __restrict__ out)
{
    __shared__ __align__(16) float tile[WTILE * ROW];
    __shared__ float ov[WTILE];

    const int bid  = blockIdx.x;
    const int n    = bid / (H_ * (W_ / WTILE));
    const int rem  = bid % (H_ * (W_ / WTILE));
    const int h    = rem / (W_ / WTILE);
    const int w0   = (rem % (W_ / WTILE)) * WTILE;
    const int tid  = threadIdx.x;
    const int lane = tid & 31;
    const int warp = tid >> 5;

    const size_t pixbase = (size_t)n * HW_ + (size_t)h * W_ + w0;

    // read scratch rows (coalesced float4) -> smem, then zero scratch
    float4* scr4 = (float4*)(g_scr + pixbase * C_);
    #pragma unroll
    for (int it = 0; it < 4; it++) {
        const int idx = it * 256 + tid;      // 0..1023
        const int p = idx >> 5, g = idx & 31;
        float4 v = scr4[p * 32 + g];
        *(float4*)&tile[p * ROW + g * 4] = v;
        scr4[p * 32 + g] = make_float4(0.f, 0.f, 0.f, 0.f);
    }
    if (tid < WTILE) {
        ov[tid] = g_oscr[pixbase + tid];
        g_oscr[pixbase + tid] = 0.f;
    }
    __syncthreads();

    // transpose out: imgw (first half of d_out), o broadcast (second half)
    float* out_img = out + ((size_t)n * C_ * H_ + h) * (size_t)W_ + w0;
    float* out_o   = out_img + (size_t)TOTAL_;
    #pragma unroll
    for (int cb = 0; cb < C_; cb += 8) {
        const int c = cb + warp;
        const size_t o = (size_t)c * HW_ + lane;
        out_img[o] = tile[lane * ROW + c];
        out_o[o]   = ov[lane];
    }
}

extern "C" void kernel_launch(void* const* d_in, const int* in_sizes, int n_in,
                              void* d_out, int out_size)
{
    const float* img;
    const float* flo;
    if (in_sizes[0] == TOTAL_) { img = (const float*)d_in[0]; flo = (const float*)d_in[1]; }
    else                       { img = (const float*)d_in[1]; flo = (const float*)d_in[0]; }
    float* out = (float*)d_out;

    scatter_kernel<<<CTAS, 256>>>(img, flo);
    gather_kernel<<<CTAS, 256>>>(out);
}

// round 7
// speedup vs baseline: 1.4832x; 1.4832x over previous
#include <cuda_runtime.h>
#include <cstdint>

#define N_  4
#define C_  128
#define H_  216
#define W_  384
#define HW_ (H_ * W_)          // 82944
#define NHW_ (N_ * HW_)        // 331776
#define TOTAL_ (N_ * C_ * HW_) // 42467328

// ---------------- scatter config (unchanged from R2) ----------------
#define PAD 4
#define ROW (C_ + PAD)         // 132
#define WTILE 32
#define SCTAS (N_ * H_ * (W_ / WTILE))  // 10368

// ---------------- gather config (new) ----------------
#define GT 128                 // pixels per gather tile
#define GCH 64                 // channels per half
#define GPP 132                // padded pixel stride in smem (c-major layout)
#define GCTAS (N_ * H_ * (W_ / GT))     // 2592

// NHWC accumulation scratch (zeroed at module load; re-zeroed by gather each
// iteration so graph replays are deterministic).
__device__ float g_scr[TOTAL_];
__device__ float g_oscr[NHW_];

__device__ __forceinline__ void red_add_v4(float* p, float a, float b, float c, float d) {
    asm volatile("red.global.add.v4.f32 [%0], {%1,%2,%3,%4};"
                 :: "l"(p), "f"(a), "f"(b), "f"(c), "f"(d) : "memory");
}
__device__ __forceinline__ void red_add_f32(float* p, float a) {
    asm volatile("red.global.add.f32 [%0], %1;" :: "l"(p), "f"(a) : "memory");
}

// ---------------------------------------------------------------------------
// Kernel 1: scatter.  CTA = 32 consecutive w of one (n, h) row.
// Load img NCHW coalesced -> smem [pix][c] -> per-pixel float4 RED scatter
// into NHWC scratch.  o accumulated per-pixel into g_oscr.
// ---------------------------------------------------------------------------
__global__ __launch_bounds__(256) void scatter_kernel(
    const float* __restrict__ img, const float* __restrict__ flo)
{
    __shared__ __align__(16) float tile[WTILE * ROW];

    const int bid  = blockIdx.x;
    const int n    = bid / (H_ * (W_ / WTILE));
    const int rem  = bid % (H_ * (W_ / WTILE));
    const int h    = rem / (W_ / WTILE);
    const int w0   = (rem % (W_ / WTILE)) * WTILE;
    const int tid  = threadIdx.x;
    const int lane = tid & 31;
    const int warp = tid >> 5;

    const float* src = img + ((size_t)n * C_ * H_ + h) * (size_t)W_ + w0;
    #pragma unroll
    for (int cb = 0; cb < C_; cb += 8) {
        int c = cb + warp;
        tile[lane * ROW + c] = src[(size_t)c * HW_ + lane];
    }
    __syncthreads();

    const float* flo_y = flo + ((size_t)n * 2) * HW_ + h * W_ + w0;   // shifts W
    const float* flo_x = flo_y + HW_;                                  // shifts H
    float* const base_n = g_scr + (size_t)n * HW_ * C_;
    float* const obase  = g_oscr + (size_t)n * HW_;

    #pragma unroll
    for (int i = 0; i < 4; i++) {
        const int p = warp * 4 + i;
        const int w = w0 + p;

        const float fy = flo_y[p];
        const float fx = flo_x[p];
        const float x1f = floorf(fx), y1f = floorf(fy);
        const float dx = fx - x1f, dy = fy - y1f;
        const int th0 = h + (int)x1f;
        const int tw0 = w + (int)y1f;

        const float ex0 = __expf(-dx * dx);
        const float ex1 = __expf(-(dx - 1.f) * (dx - 1.f));
        const float ey0 = __expf(-dy * dy);
        const float ey1 = __expf(-(dy - 1.f) * (dy - 1.f));

        const float4 v = *(const float4*)&tile[p * ROW + lane * 4];

        #pragma unroll
        for (int ci = 0; ci < 2; ci++) {
            const int th = th0 + ci;
            if (th < 0 || th >= H_) continue;
            const float exi = ci ? ex1 : ex0;
            #pragma unroll
            for (int cj = 0; cj < 2; cj++) {
                const int tw = tw0 + cj;
                if (tw < 0 || tw >= W_) continue;
                const float wt = exi * (cj ? ey1 : ey0);
                float* dst = base_n + ((size_t)th * W_ + tw) * C_ + lane * 4;
                red_add_v4(dst, v.x * wt, v.y * wt, v.z * wt, v.w * wt);
                if (lane == 0)
                    red_add_f32(obase + th * W_ + tw, wt);
            }
        }
    }
}

// ---------------------------------------------------------------------------
// Kernel 2: gather (rewritten).  CTA = 128 consecutive w of one (n, h) row,
// 512 threads.  Channels processed in two 64-channel halves.
//   Phase A: read scratch NHWC (float4, streaming), zero it behind the read,
//            transpose into smem in channel-major layout tile[c][pix].
//   Phase B: conflict-free LDS.128 along pixels -> STG.128 512B-per-warp
//            contiguous stores into NCHW output; o broadcast likewise.
// ---------------------------------------------------------------------------
__global__ __launch_bounds__(512) void gather_kernel(float* __restrict__ out)
{
    __shared__ __align__(16) float tile[GCH * GPP];   // 64 * 132 * 4 = 33792 B
    __shared__ __align__(16) float ovs[GT];           // 512 B

    const int bid  = blockIdx.x;
    const int n    = bid / (H_ * (W_ / GT));
    const int rem  = bid % (H_ * (W_ / GT));
    const int h    = rem / (W_ / GT);
    const int w0   = (rem % (W_ / GT)) * GT;
    const int tid  = threadIdx.x;
    const int lane = tid & 31;
    const int warp = tid >> 5;

    const size_t pixbase = (size_t)n * HW_ + (size_t)h * W_ + w0;
    float4* const scr4 = (float4*)(g_scr + pixbase * C_);   // 128 pix * 32 quads

    float* const out_img_base = out + ((size_t)n * C_ * H_ + h) * (size_t)W_ + w0;
    float* const out_o_base   = out_img_base + (size_t)TOTAL_;

    // o values for these 128 pixels (read + zero once)
    if (tid < GT) {
        ovs[tid] = g_oscr[pixbase + tid];
        g_oscr[pixbase + tid] = 0.f;
    }

    float4 ov4;   // valid after first barrier

    #pragma unroll
    for (int half = 0; half < 2; half++) {
        // ---- phase A: 128 pixels x 64 channels, load + zero + transpose ----
        #pragma unroll
        for (int it = 0; it < 4; it++) {
            const int idx = it * 512 + tid;      // 0..2047
            const int p = idx >> 4;              // pixel 0..127
            const int q = idx & 15;              // channel quad within half
            float4* sp = scr4 + (size_t)p * 32 + half * 16 + q;
            float4 v;
            asm volatile("ld.global.cs.v4.f32 {%0,%1,%2,%3}, [%4];"
                         : "=f"(v.x), "=f"(v.y), "=f"(v.z), "=f"(v.w) : "l"(sp));
            asm volatile("st.global.cs.v4.f32 [%0], {%1,%2,%3,%4};"
                         :: "l"(sp), "f"(0.f), "f"(0.f), "f"(0.f), "f"(0.f) : "memory");
            const int c0 = q * 4;
            tile[(c0 + 0) * GPP + p] = v.x;
            tile[(c0 + 1) * GPP + p] = v.y;
            tile[(c0 + 2) * GPP + p] = v.z;
            tile[(c0 + 3) * GPP + p] = v.w;
        }
        __syncthreads();
        if (half == 0)
            ov4 = *(const float4*)&ovs[lane * 4];

        // ---- phase B: write 64 channels, 512B contiguous per warp-visit ----
        #pragma unroll
        for (int cb = 0; cb < 4; cb++) {
            const int cl = cb * 16 + warp;           // channel within half
            const int c  = half * GCH + cl;          // global channel
            const float4 v = *(const float4*)&tile[cl * GPP + lane * 4];
            float* pi = out_img_base + (size_t)c * HW_ + lane * 4;
            float* po = out_o_base   + (size_t)c * HW_ + lane * 4;
            asm volatile("st.global.cs.v4.f32 [%0], {%1,%2,%3,%4};"
                         :: "l"(pi), "f"(v.x), "f"(v.y), "f"(v.z), "f"(v.w) : "memory");
            asm volatile("st.global.cs.v4.f32 [%0], {%1,%2,%3,%4};"
                         :: "l"(po), "f"(ov4.x), "f"(ov4.y), "f"(ov4.z), "f"(ov4.w) : "memory");
        }
        __syncthreads();
    }
}

extern "C" void kernel_launch(void* const* d_in, const int* in_sizes, int n_in,
                              void* d_out, int out_size)
{
    const float* img;
    const float* flo;
    if (in_sizes[0] == TOTAL_) { img = (const float*)d_in[0]; flo = (const float*)d_in[1]; }
    else                       { img = (const float*)d_in[1]; flo = (const float*)d_in[0]; }
    float* out = (float*)d_out;

    scatter_kernel<<<SCTAS, 256>>>(img, flo);
    gather_kernel<<<GCTAS, 512>>>(out);
}

// round 9
// speedup vs baseline: 1.5223x; 1.0264x over previous
#include <cuda_runtime.h>
#include <cstdint>

#define N_  4
#define C_  128
#define H_  216
#define W_  384
#define HW_ (H_ * W_)          // 82944
#define NHW_ (N_ * HW_)        // 331776
#define TOTAL_ (N_ * C_ * HW_) // 42467328

// ---------------- scatter config (unchanged) ----------------
#define PAD 4
#define ROW (C_ + PAD)         // 132
#define WTILE 32
#define SCTAS (N_ * H_ * (W_ / WTILE))  // 10368

// ---------------- gather config ----------------
#define GT 128                 // pixels per gather tile
#define GPP 132                // padded pixel stride (floats) in smem, c-major
#define GCTAS (N_ * H_ * (W_ / GT))     // 2592
#define GSMEM (C_ * GPP * 4 + GT * 4)   // 67584 + 512 = 68096 B

// NHWC accumulation scratch (zeroed at module load; re-zeroed by gather each
// iteration so graph replays are deterministic).
__device__ __align__(16) float g_scr[TOTAL_];
__device__ __align__(16) float g_oscr[NHW_];

__device__ __forceinline__ void red_add_v4(float* p, float a, float b, float c, float d) {
    asm volatile("red.global.add.v4.f32 [%0], {%1,%2,%3,%4};"
                 :: "l"(p), "f"(a), "f"(b), "f"(c), "f"(d) : "memory");
}
__device__ __forceinline__ void red_add_f32(float* p, float a) {
    asm volatile("red.global.add.f32 [%0], %1;" :: "l"(p), "f"(a) : "memory");
}

// ---------------------------------------------------------------------------
// Kernel 1: scatter (unchanged).
// ---------------------------------------------------------------------------
__global__ __launch_bounds__(256) void scatter_kernel(
    const float* __restrict__ img, const float* __restrict__ flo)
{
    __shared__ __align__(16) float tile[WTILE * ROW];

    const int bid  = blockIdx.x;
    const int n    = bid / (H_ * (W_ / WTILE));
    const int rem  = bid % (H_ * (W_ / WTILE));
    const int h    = rem / (W_ / WTILE);
    const int w0   = (rem % (W_ / WTILE)) * WTILE;
    const int tid  = threadIdx.x;
    const int lane = tid & 31;
    const int warp = tid >> 5;

    const float* src = img + ((size_t)n * C_ * H_ + h) * (size_t)W_ + w0;
    #pragma unroll
    for (int cb = 0; cb < C_; cb += 8) {
        int c = cb + warp;
        tile[lane * ROW + c] = src[(size_t)c * HW_ + lane];
    }
    __syncthreads();

    const float* flo_y = flo + ((size_t)n * 2) * HW_ + h * W_ + w0;   // shifts W
    const float* flo_x = flo_y + HW_;                                  // shifts H
    float* const base_n = g_scr + (size_t)n * HW_ * C_;
    float* const obase  = g_oscr + (size_t)n * HW_;

    #pragma unroll
    for (int i = 0; i < 4; i++) {
        const int p = warp * 4 + i;
        const int w = w0 + p;

        const float fy = flo_y[p];
        const float fx = flo_x[p];
        const float x1f = floorf(fx), y1f = floorf(fy);
        const float dx = fx - x1f, dy = fy - y1f;
        const int th0 = h + (int)x1f;
        const int tw0 = w + (int)y1f;

        const float ex0 = __expf(-dx * dx);
        const float ex1 = __expf(-(dx - 1.f) * (dx - 1.f));
        const float ey0 = __expf(-dy * dy);
        const float ey1 = __expf(-(dy - 1.f) * (dy - 1.f));

        const float4 v = *(const float4*)&tile[p * ROW + lane * 4];

        #pragma unroll
        for (int ci = 0; ci < 2; ci++) {
            const int th = th0 + ci;
            if (th < 0 || th >= H_) continue;
            const float exi = ci ? ex1 : ex0;
            #pragma unroll
            for (int cj = 0; cj < 2; cj++) {
                const int tw = tw0 + cj;
                if (tw < 0 || tw >= W_) continue;
                const float wt = exi * (cj ? ey1 : ey0);
                float* dst = base_n + ((size_t)th * W_ + tw) * C_ + lane * 4;
                red_add_v4(dst, v.x * wt, v.y * wt, v.z * wt, v.w * wt);
                if (lane == 0)
                    red_add_f32(obase + th * W_ + tw, wt);
            }
        }
    }
}

// ---------------------------------------------------------------------------
// Kernel 2: gather (single full-C pass, swizzle FIXED).
// CTA = 128 consecutive w of one (n, h) row, 512 threads, 68KB dynamic smem.
//   Phase A: 8 INDEPENDENT ld.cs float4 (MLP=8), then 8 st.cs zeros, then
//            transpose into c-major smem with XOR column swizzle (2-way STS).
//   Phase B: swizzled LDS.128 self-deswizzles (entry i holds pixel i^s, so
//            the float4 at psw=(lane*4)^s is exactly pixels lane*4..lane*4+3);
//            global stores therefore use the PLAIN lane*4 offset.
// ---------------------------------------------------------------------------
__global__ __launch_bounds__(512, 2) void gather_kernel(float* __restrict__ out)
{
    extern __shared__ __align__(16) float smem[];
    float* const tile = smem;                 // [C_][GPP]
    float* const ovs  = smem + C_ * GPP;      // [GT]

    const int bid  = blockIdx.x;
    const int n    = bid / (H_ * (W_ / GT));
    const int rem  = bid % (H_ * (W_ / GT));
    const int h    = rem / (W_ / GT);
    const int w0   = (rem % (W_ / GT)) * GT;
    const int tid  = threadIdx.x;
    const int lane = tid & 31;
    const int warp = tid >> 5;

    const size_t pixbase = (size_t)n * HW_ + (size_t)h * W_ + w0;
    float4* const scr4 = (float4*)(g_scr + pixbase * C_);   // 128 pix * 32 quads

    float* const out_img_base = out + ((size_t)n * C_ * H_ + h) * (size_t)W_ + w0;
    float* const out_o_base   = out_img_base + (size_t)TOTAL_;

    // ---- phase A: 8 independent streaming loads ----
    float4 v[8];
    int   off[8];
    #pragma unroll
    for (int it = 0; it < 8; it++) {
        const int idx = it * 512 + tid;                     // 0..4095
        const int p   = (idx >> 4) & 127;                   // pixel
        const int q   = ((idx >> 11) << 4) | (idx & 15);    // channel quad 0..31
        off[it] = p * 32 + q;
        v[it]   = __ldcs(scr4 + off[it]);
    }
    // zero scratch behind the reads (same addresses; per-thread order is safe)
    const float4 z4 = make_float4(0.f, 0.f, 0.f, 0.f);
    #pragma unroll
    for (int it = 0; it < 8; it++)
        __stcs(scr4 + off[it], z4);

    // o values for these 128 pixels (read + zero once)
    if (tid < GT) {
        ovs[tid] = __ldcs(g_oscr + pixbase + tid);
        __stcs(g_oscr + pixbase + tid, 0.f);
    }

    // transpose into smem: tile[c][ p ^ ((q&7)<<2) ]  (2-way STS conflicts)
    #pragma unroll
    for (int it = 0; it < 8; it++) {
        const int p  = off[it] >> 5;
        const int q  = off[it] & 31;
        const int ps = p ^ ((q & 7) << 2);
        const int c0 = q * 4;
        tile[(c0 + 0) * GPP + ps] = v[it].x;
        tile[(c0 + 1) * GPP + ps] = v[it].y;
        tile[(c0 + 2) * GPP + ps] = v[it].z;
        tile[(c0 + 3) * GPP + ps] = v[it].w;
    }
    __syncthreads();

    // ---- phase B: 8 channel-visits per warp, 512B contiguous stores ----
    #pragma unroll
    for (int cb = 0; cb < 8; cb++) {
        const int cl  = cb * 16 + warp;                    // channel 0..127
        const int qc  = cl >> 2;
        const int psw = (lane * 4) ^ ((qc & 7) << 2);      // swizzled smem index
        // float4 at psw holds pixels lane*4 .. lane*4+3 (self-deswizzled)
        const float4 vv = *(const float4*)&tile[cl * GPP + psw];
        const float4 ov = *(const float4*)&ovs[lane * 4];
        __stcs((float4*)(out_img_base + (size_t)cl * HW_ + lane * 4), vv);
        __stcs((float4*)(out_o_base   + (size_t)cl * HW_ + lane * 4), ov);
    }
}

extern "C" void kernel_launch(void* const* d_in, const int* in_sizes, int n_in,
                              void* d_out, int out_size)
{
    const float* img;
    const float* flo;
    if (in_sizes[0] == TOTAL_) { img = (const float*)d_in[0]; flo = (const float*)d_in[1]; }
    else                       { img = (const float*)d_in[1]; flo = (const float*)d_in[0]; }
    float* out = (float*)d_out;

    // >48KB static limit: opt in to large dynamic smem (host-side attribute,
    // executes on the capture call itself; not a graph node, no allocation).
    cudaFuncSetAttribute(gather_kernel,
                         cudaFuncAttributeMaxDynamicSharedMemorySize, GSMEM);

    scatter_kernel<<<SCTAS, 256>>>(img, flo);
    gather_kernel<<<GCTAS, 512, GSMEM>>>(out);
}

// round 10
// speedup vs baseline: 2.4257x; 1.5934x over previous
#include <cuda_runtime.h>
#include <cstdint>

#define N_  4
#define C_  128
#define H_  216
#define W_  384
#define HW_ (H_ * W_)          // 82944
#define NHW_ (N_ * HW_)        // 331776
#define TOTAL_ (N_ * C_ * HW_) // 42467328

// ---------------- scatter config ----------------
#define PAD 4
#define ROW (C_ + PAD)         // 132
#define WTILE 32
#define SCTAS (H_ * (W_ / WTILE))       // 2592 per batch

// ---------------- gather config ----------------
#define GT 128                 // pixels per gather tile
#define GPP 132                // padded pixel stride (floats) in smem, c-major
#define GCTAS (H_ * (W_ / GT))          // 648 per batch
#define GSMEM (C_ * GPP * 4 + GT * 4)   // 68096 B

// NHWC accumulation scratch (zeroed at module load; re-zeroed by gather each
// iteration so graph replays are deterministic).
__device__ __align__(16) float g_scr[TOTAL_];
__device__ __align__(16) float g_oscr[NHW_];

__device__ __forceinline__ void red_add_v4(float* p, float a, float b, float c, float d) {
    asm volatile("red.global.add.v4.f32 [%0], {%1,%2,%3,%4};"
                 :: "l"(p), "f"(a), "f"(b), "f"(c), "f"(d) : "memory");
}
__device__ __forceinline__ void red_add_f32(float* p, float a) {
    asm volatile("red.global.add.f32 [%0], %1;" :: "l"(p), "f"(a) : "memory");
}

// ---------------------------------------------------------------------------
// Kernel 1: scatter for ONE batch n.  CTA = 32 consecutive w of one h row.
// img/flow loads are streaming (.cs) so they don't evict scratch from L2.
// ---------------------------------------------------------------------------
__global__ __launch_bounds__(256) void scatter_kernel(
    const float* __restrict__ img, const float* __restrict__ flo, const int n)
{
    __shared__ __align__(16) float tile[WTILE * ROW];

    const int bid  = blockIdx.x;
    const int h    = bid / (W_ / WTILE);
    const int w0   = (bid % (W_ / WTILE)) * WTILE;
    const int tid  = threadIdx.x;
    const int lane = tid & 31;
    const int warp = tid >> 5;

    const float* src = img + ((size_t)n * C_ * H_ + h) * (size_t)W_ + w0;
    #pragma unroll
    for (int cb = 0; cb < C_; cb += 8) {
        int c = cb + warp;
        tile[lane * ROW + c] = __ldcs(src + (size_t)c * HW_ + lane);
    }
    __syncthreads();

    const float* flo_y = flo + ((size_t)n * 2) * HW_ + h * W_ + w0;   // shifts W
    const float* flo_x = flo_y + HW_;                                  // shifts H
    float* const base_n = g_scr + (size_t)n * HW_ * C_;
    float* const obase  = g_oscr + (size_t)n * HW_;

    #pragma unroll
    for (int i = 0; i < 4; i++) {
        const int p = warp * 4 + i;
        const int w = w0 + p;

        const float fy = __ldcs(flo_y + p);
        const float fx = __ldcs(flo_x + p);
        const float x1f = floorf(fx), y1f = floorf(fy);
        const float dx = fx - x1f, dy = fy - y1f;
        const int th0 = h + (int)x1f;
        const int tw0 = w + (int)y1f;

        const float ex0 = __expf(-dx * dx);
        const float ex1 = __expf(-(dx - 1.f) * (dx - 1.f));
        const float ey0 = __expf(-dy * dy);
        const float ey1 = __expf(-(dy - 1.f) * (dy - 1.f));

        const float4 v = *(const float4*)&tile[p * ROW + lane * 4];

        #pragma unroll
        for (int ci = 0; ci < 2; ci++) {
            const int th = th0 + ci;
            if (th < 0 || th >= H_) continue;
            const float exi = ci ? ex1 : ex0;
            #pragma unroll
            for (int cj = 0; cj < 2; cj++) {
                const int tw = tw0 + cj;
                if (tw < 0 || tw >= W_) continue;
                const float wt = exi * (cj ? ey1 : ey0);
                float* dst = base_n + ((size_t)th * W_ + tw) * C_ + lane * 4;
                red_add_v4(dst, v.x * wt, v.y * wt, v.z * wt, v.w * wt);
                if (lane == 0)
                    red_add_f32(obase + th * W_ + tw, wt);
            }
        }
    }
}

// ---------------------------------------------------------------------------
// Kernel 2: gather for ONE batch n (runs in a forked stream, overlapped with
// the next batch's scatter; scratch for batch n is L2-warm).
//   Phase A: 8 INDEPENDENT ld.cs float4 (MLP=8), then 8 st.cs zeros, then
//            transpose into c-major smem with XOR column swizzle (2-way STS).
//   Phase B: swizzled LDS.128 self-deswizzles; plain lane*4 global offsets.
// ---------------------------------------------------------------------------
__global__ __launch_bounds__(512, 2) void gather_kernel(float* __restrict__ out,
                                                        const int n)
{
    extern __shared__ __align__(16) float smem[];
    float* const tile = smem;                 // [C_][GPP]
    float* const ovs  = smem + C_ * GPP;      // [GT]

    const int bid  = blockIdx.x;
    const int h    = bid / (W_ / GT);
    const int w0   = (bid % (W_ / GT)) * GT;
    const int tid  = threadIdx.x;
    const int lane = tid & 31;
    const int warp = tid >> 5;

    const size_t pixbase = (size_t)n * HW_ + (size_t)h * W_ + w0;
    float4* const scr4 = (float4*)(g_scr + pixbase * C_);   // 128 pix * 32 quads

    float* const out_img_base = out + ((size_t)n * C_ * H_ + h) * (size_t)W_ + w0;
    float* const out_o_base   = out_img_base + (size_t)TOTAL_;

    // ---- phase A: 8 independent streaming loads ----
    float4 v[8];
    int   off[8];
    #pragma unroll
    for (int it = 0; it < 8; it++) {
        const int idx = it * 512 + tid;                     // 0..4095
        const int p   = (idx >> 4) & 127;                   // pixel
        const int q   = ((idx >> 11) << 4) | (idx & 15);    // channel quad 0..31
        off[it] = p * 32 + q;
        v[it]   = __ldcs(scr4 + off[it]);
    }
    const float4 z4 = make_float4(0.f, 0.f, 0.f, 0.f);
    #pragma unroll
    for (int it = 0; it < 8; it++)
        __stcs(scr4 + off[it], z4);

    if (tid < GT) {
        ovs[tid] = __ldcs(g_oscr + pixbase + tid);
        __stcs(g_oscr + pixbase + tid, 0.f);
    }

    #pragma unroll
    for (int it = 0; it < 8; it++) {
        const int p  = off[it] >> 5;
        const int q  = off[it] & 31;
        const int ps = p ^ ((q & 7) << 2);
        const int c0 = q * 4;
        tile[(c0 + 0) * GPP + ps] = v[it].x;
        tile[(c0 + 1) * GPP + ps] = v[it].y;
        tile[(c0 + 2) * GPP + ps] = v[it].z;
        tile[(c0 + 3) * GPP + ps] = v[it].w;
    }
    __syncthreads();

    // ---- phase B: 8 channel-visits per warp, 512B contiguous stores ----
    #pragma unroll
    for (int cb = 0; cb < 8; cb++) {
        const int cl  = cb * 16 + warp;                    // channel 0..127
        const int qc  = cl >> 2;
        const int psw = (lane * 4) ^ ((qc & 7) << 2);      // swizzled smem index
        const float4 vv = *(const float4*)&tile[cl * GPP + psw];
        const float4 ov = *(const float4*)&ovs[lane * 4];
        __stcs((float4*)(out_img_base + (size_t)cl * HW_ + lane * 4), vv);
        __stcs((float4*)(out_o_base   + (size_t)cl * HW_ + lane * 4), ov);
    }
}

extern "C" void kernel_launch(void* const* d_in, const int* in_sizes, int n_in,
                              void* d_out, int out_size)
{
    const float* img;
    const float* flo;
    if (in_sizes[0] == TOTAL_) { img = (const float*)d_in[0]; flo = (const float*)d_in[1]; }
    else                       { img = (const float*)d_in[1]; flo = (const float*)d_in[0]; }
    float* out = (float*)d_out;

    // One-time setup (runs on the uncaptured correctness call; no device
    // memory is allocated — streams/events are host-side objects).
    static cudaStream_t s1 = nullptr;
    static cudaEvent_t  evS[N_], evJoin;
    if (s1 == nullptr) {
        cudaStreamCreateWithFlags(&s1, cudaStreamNonBlocking);
        for (int i = 0; i < N_; i++)
            cudaEventCreateWithFlags(&evS[i], cudaEventDisableTiming);
        cudaEventCreateWithFlags(&evJoin, cudaEventDisableTiming);
        cudaFuncSetAttribute(gather_kernel,
                             cudaFuncAttributeMaxDynamicSharedMemorySize, GSMEM);
    }

    // Pipelined per-batch: scatters back-to-back on the capture stream,
    // gathers forked onto s1 (G_n waits only on S_n). Join before return.
    for (int n = 0; n < N_; n++) {
        scatter_kernel<<<SCTAS, 256>>>(img, flo, n);
        cudaEventRecord(evS[n], 0);
        cudaStreamWaitEvent(s1, evS[n], 0);
        gather_kernel<<<GCTAS, 512, GSMEM, s1>>>(out, n);
    }
    cudaEventRecord(evJoin, s1);
    cudaStreamWaitEvent(0, evJoin, 0);
}